// round 14
// baseline (speedup 1.0000x reference)
#include <cuda_runtime.h>
#include <cuda_fp16.h>
#include <cstdint>

#define NN 100000
#define NE 6400000
#define KIN 768
#define EH  512

// ---------------- scratch (static __device__, no allocations) ----------------
__device__ float4 g_hh[(size_t)NN * 2];        // hh per node (2 heads x 3 classes)
__device__ float2 g_asrc[NN];
__device__ float2 g_adst[NN];
__device__ float4 g_acc[(size_t)NN * 2];       // (num_c0,num_c1,num_c2,denom) per head
__device__ float  g_hh6b[8][(size_t)NN * 8];   // per-(bx,wn) partial h1@Wc slices (6 used, stride 8)
__device__ float  g_Wc[EH * 6 + 8];            // fused W_e2@W_lin@W_att [512,6] + bc[6]
__device__ float  g_W2[256 * 6 + 8];           // W_lin@W_att [256,6] + bl[6]
__device__ int    g_is64;
__device__ __half g_Wh[(size_t)EH * KIN];      // W_e1^T fp16 [512][768]

__device__ __forceinline__ float lrelu(float x) { return x >= 0.f ? x : 0.2f * x; }

__device__ __forceinline__ uint32_t smem_u32(const void* p) {
    uint32_t a;
    asm("{ .reg .u64 t; cvta.to.shared.u64 t, %1; cvt.u32.u64 %0, t; }" : "=r"(a) : "l"(p));
    return a;
}

#define LDSM4(r0, r1, r2, r3, addr) \
    asm volatile("ldmatrix.sync.aligned.m8n8.x4.shared.b16 {%0,%1,%2,%3}, [%4];" \
                 : "=r"(r0), "=r"(r1), "=r"(r2), "=r"(r3) : "r"(addr))

#define MMA16816(c, a0, a1, a2, a3, b0, b1) \
    asm volatile("mma.sync.aligned.m16n8k16.row.col.f32.f16.f16.f32 " \
                 "{%0,%1,%2,%3},{%4,%5,%6,%7},{%8,%9},{%0,%1,%2,%3};" \
                 : "+f"((c)[0]), "+f"((c)[1]), "+f"((c)[2]), "+f"((c)[3]) \
                 : "r"(a0), "r"(a1), "r"(a2), "r"(a3), "r"(b0), "r"(b1))

#define CP_ASYNC16(dst, src) \
    asm volatile("cp.async.cg.shared.global [%0], [%1], 16;" :: "r"(dst), "l"(src))
#define CP_COMMIT() asm volatile("cp.async.commit_group;")
#define CP_WAIT0()  asm volatile("cp.async.wait_group 0;")

// ---------------- K_detect: edge_index dtype ----------------
__global__ void k_detect(const void* __restrict__ ei) {
    const long long* p = (const long long*)ei;
    int bad = 0;
    for (int i = threadIdx.x; i < 2048; i += 256) {
        long long v = p[i];
        if (v < 0 || v >= NN) bad = 1;
    }
    bad = __syncthreads_or(bad);
    if (threadIdx.x == 0) g_is64 = !bad;
}

// ---------------- K_wt: W_e1 [768][512] -> W^T fp16 [512][768] ----------------
__global__ void k_wt(const float* __restrict__ W) {
    int i = blockIdx.x * 256 + threadIdx.x;  // 0..393215
    int k = i >> 9, n = i & 511;
    g_Wh[(size_t)n * KIN + k] = __float2half_rn(W[i]);
}

// ---------------- K0a: W2 = W_lin@W_att [256,6], bl [6] ----------------
__global__ void k0a(const float* __restrict__ W_lin, const float* __restrict__ b_lin,
                    const float* __restrict__ W_att) {
    int t = threadIdx.x;  // 256
    float a[6] = {0, 0, 0, 0, 0, 0};
    for (int j = 0; j < 32; ++j) {
        float w = W_lin[t * 32 + j];
        #pragma unroll
        for (int c = 0; c < 6; ++c) a[c] += w * W_att[j * 6 + c];
    }
    #pragma unroll
    for (int c = 0; c < 6; ++c) g_W2[t * 6 + c] = a[c];
    if (t < 6) {
        float s = 0.f;
        for (int j = 0; j < 32; ++j) s += b_lin[j] * W_att[j * 6 + t];
        g_W2[256 * 6 + t] = s;
    }
}

// ---------------- K0b: Wc = W_e2@W2 [512,6], bc [6]  (grid 16 x 32 rows) ----------------
__global__ void k0b(const float* __restrict__ W_e2, const float* __restrict__ b_e2) {
    __shared__ float W2s[256 * 6];
    int t = threadIdx.x;  // 256
    #pragma unroll
    for (int j = 0; j < 6; ++j) W2s[t * 6 + j] = g_W2[t * 6 + j];
    __syncthreads();
    int row = blockIdx.x * 32 + (t >> 3);
    int seg = t & 7;                         // 32 k-values each
    float a[6] = {0, 0, 0, 0, 0, 0};
    const float4* wr = (const float4*)(W_e2 + (size_t)row * 256 + seg * 32);
    #pragma unroll
    for (int q = 0; q < 8; ++q) {
        float4 w = wr[q];
        int k = seg * 32 + q * 4;
        #pragma unroll
        for (int c = 0; c < 6; ++c)
            a[c] += w.x * W2s[k * 6 + c] + w.y * W2s[(k + 1) * 6 + c]
                  + w.z * W2s[(k + 2) * 6 + c] + w.w * W2s[(k + 3) * 6 + c];
    }
    #pragma unroll
    for (int o = 4; o > 0; o >>= 1)
        #pragma unroll
        for (int c = 0; c < 6; ++c) a[c] += __shfl_xor_sync(0xffffffffu, a[c], o);
    if (seg == 0)
        #pragma unroll
        for (int c = 0; c < 6; ++c) g_Wc[row * 6 + c] = a[c];
    if (blockIdx.x == 0 && t < 6) {
        float s = 0.f;
        for (int k = 0; k < 256; ++k) s += b_e2[k] * g_W2[k * 6 + t];
        g_Wc[EH * 6 + t] = s + g_W2[256 * 6 + t];
    }
}

// ---------------- K1: fp16 GEMM (fused fp32->fp16 A convert) + relu + Wc contraction ----------------
// 128x128 tile, BK=32, double-buffered. A: LDG fp32 + reg-convert + STS; B: cp.async fp16.
#define RS 40                       // smem row stride in halves (32 + 8 pad)
#define TILEB (128 * RS * 2)        // 10240 bytes per tile
#define STAGEB (2 * TILEB)          // A (fp16), B

__global__ __launch_bounds__(256, 1)
void k1_mma(const float* __restrict__ X, const float* __restrict__ Bb) {
    extern __shared__ __align__(16) uint8_t sm[];
    __shared__ float s_bias[128];
    __shared__ float s_wc[128 * 6];

    const int tid = threadIdx.x;
    const int wid = tid >> 5, lane = tid & 31;
    const int wm = wid & 3, wn = wid >> 2;
    const int m0 = blockIdx.y * 128;
    const int n0 = blockIdx.x * 128;
    const uint32_t smb = smem_u32(sm);

    if (tid < 128) s_bias[tid] = Bb[n0 + tid];
    for (int i = tid; i < 128 * 6; i += 256) s_wc[i] = g_Wc[n0 * 6 + i];

    // A: 2 threads/row, 16 fp32 each (4x float4)
    const int ar = tid >> 1, ac = (tid & 1) * 16;
    int arow = m0 + ar; if (arow >= NN) arow = NN - 1;
    const float* Abase = X + (size_t)arow * KIN + ac;
    // B: cp.async, 4 threads/row
    const int cc = tid & 3;

    auto ldgA = [&](int s, float4* v) {
        const float4* p = (const float4*)(Abase + s * 32);
        v[0] = p[0]; v[1] = p[1]; v[2] = p[2]; v[3] = p[3];
    };
    auto stsA = [&](int st, const float4* v) {
        __half2 h0 = __floats2half2_rn(v[0].x, v[0].y);
        __half2 h1 = __floats2half2_rn(v[0].z, v[0].w);
        __half2 h2 = __floats2half2_rn(v[1].x, v[1].y);
        __half2 h3 = __floats2half2_rn(v[1].z, v[1].w);
        __half2 h4 = __floats2half2_rn(v[2].x, v[2].y);
        __half2 h5 = __floats2half2_rn(v[2].z, v[2].w);
        __half2 h6 = __floats2half2_rn(v[3].x, v[3].y);
        __half2 h7 = __floats2half2_rn(v[3].z, v[3].w);
        uint32_t off = st * STAGEB + (ar * RS + ac) * 2;
        *(uint4*)(sm + off) = make_uint4(*(uint32_t*)&h0, *(uint32_t*)&h1,
                                         *(uint32_t*)&h2, *(uint32_t*)&h3);
        *(uint4*)(sm + off + 16) = make_uint4(*(uint32_t*)&h4, *(uint32_t*)&h5,
                                              *(uint32_t*)&h6, *(uint32_t*)&h7);
    };
    auto loadB = [&](int st, int s) {
        uint32_t base = smb + st * STAGEB + TILEB;
        int k0 = s * 32;
        #pragma unroll
        for (int j = 0; j < 2; ++j) {
            int r = j * 64 + (tid >> 2);
            const __half* src = g_Wh + (size_t)(n0 + r) * KIN + k0 + cc * 8;
            uint32_t dst = base + (r * RS + cc * 8) * 2;
            CP_ASYNC16(dst, src);
        }
        CP_COMMIT();
    };

    float c[2][8][4];
    #pragma unroll
    for (int mi = 0; mi < 2; ++mi)
        #pragma unroll
        for (int ni = 0; ni < 8; ++ni)
            #pragma unroll
            for (int q = 0; q < 4; ++q) c[mi][ni][q] = 0.f;

    float4 av[4];
    ldgA(0, av);
    loadB(0, 0);
    stsA(0, av);
    CP_WAIT0();
    __syncthreads();

    int buf = 0;
    for (int s = 0; s < 24; ++s) {
        if (s + 1 < 24) { ldgA(s + 1, av); loadB(buf ^ 1, s + 1); }

        uint32_t base = smb + buf * STAGEB;
        const int arw = wm * 32 + (lane & 15);
        const int acolh = ((lane >> 4) & 1) * 8;
        const int brw = wn * 64 + ((lane >> 4) & 1) * 8 + (lane & 7);
        const int bcolh = ((lane >> 3) & 1) * 8;

        #pragma unroll
        for (int kq = 0; kq < 2; ++kq) {
            int k16 = kq * 16;
            uint32_t ah[2][4], bh[8][2];
            #pragma unroll
            for (int mi = 0; mi < 2; ++mi) {
                uint32_t aoff = ((arw + mi * 16) * RS + k16 + acolh) * 2;
                LDSM4(ah[mi][0], ah[mi][1], ah[mi][2], ah[mi][3], base + aoff);
            }
            #pragma unroll
            for (int nj = 0; nj < 4; ++nj) {
                uint32_t boff = ((brw + nj * 16) * RS + k16 + bcolh) * 2;
                LDSM4(bh[2 * nj][0], bh[2 * nj][1], bh[2 * nj + 1][0], bh[2 * nj + 1][1],
                      base + TILEB + boff);
            }
            #pragma unroll
            for (int mi = 0; mi < 2; ++mi)
                #pragma unroll
                for (int ni = 0; ni < 8; ++ni)
                    MMA16816(c[mi][ni], ah[mi][0], ah[mi][1], ah[mi][2], ah[mi][3],
                             bh[ni][0], bh[ni][1]);
        }

        if (s + 1 < 24) { stsA(buf ^ 1, av); CP_WAIT0(); }
        __syncthreads();
        buf ^= 1;
    }

    // epilogue: bias + relu, contract against Wc[128,6], quad-reduce,
    // plain store to slice (bx*2 + wn) — each wn-half owns its own slice (no race)
    float hp[2][2][6];
    #pragma unroll
    for (int mi = 0; mi < 2; ++mi)
        #pragma unroll
        for (int r = 0; r < 2; ++r)
            #pragma unroll
            for (int k = 0; k < 6; ++k) hp[mi][r][k] = 0.f;

    const int lcolq = (lane & 3) * 2;
    #pragma unroll
    for (int mi = 0; mi < 2; ++mi)
        #pragma unroll
        for (int ni = 0; ni < 8; ++ni) {
            int colL = wn * 64 + ni * 8 + lcolq;
            float b0 = s_bias[colL], b1 = s_bias[colL + 1];
            float v00 = fmaxf(c[mi][ni][0] + b0, 0.f);
            float v01 = fmaxf(c[mi][ni][1] + b1, 0.f);
            float v10 = fmaxf(c[mi][ni][2] + b0, 0.f);
            float v11 = fmaxf(c[mi][ni][3] + b1, 0.f);
            #pragma unroll
            for (int k = 0; k < 6; ++k) {
                float w0 = s_wc[colL * 6 + k], w1 = s_wc[(colL + 1) * 6 + k];
                hp[mi][0][k] += v00 * w0 + v01 * w1;
                hp[mi][1][k] += v10 * w0 + v11 * w1;
            }
        }
    #pragma unroll
    for (int mi = 0; mi < 2; ++mi)
        #pragma unroll
        for (int r = 0; r < 2; ++r)
            #pragma unroll
            for (int k = 0; k < 6; ++k) {
                float v = hp[mi][r][k];
                v += __shfl_xor_sync(0xffffffffu, v, 1);
                v += __shfl_xor_sync(0xffffffffu, v, 2);
                hp[mi][r][k] = v;
            }
    if ((lane & 3) == 0) {
        float* slice = g_hh6b[blockIdx.x * 2 + wn];
        #pragma unroll
        for (int mi = 0; mi < 2; ++mi)
            #pragma unroll
            for (int r = 0; r < 2; ++r) {
                int row = m0 + wm * 32 + mi * 16 + r * 8 + (lane >> 2);
                if (row < NN) {
                    float* dst = slice + (size_t)row * 8;
                    *(float4*)dst = make_float4(hp[mi][r][0], hp[mi][r][1],
                                                hp[mi][r][2], hp[mi][r][3]);
                    *(float2*)(dst + 4) = make_float2(hp[mi][r][4], hp[mi][r][5]);
                }
            }
    }
}

// ---------------- K2b: sum 8 slices, node finalize (a_src/a_dst, self-loop init) ----------------
__global__ __launch_bounds__(256)
void k2b(const float* __restrict__ att_src, const float* __restrict__ att_dst) {
    int n = blockIdx.x * 256 + threadIdx.x;
    if (n >= NN) return;
    float hh[6];
    #pragma unroll
    for (int c = 0; c < 6; ++c) hh[c] = g_Wc[EH * 6 + c];
    #pragma unroll
    for (int b = 0; b < 8; ++b) {
        const float* p = g_hh6b[b] + (size_t)n * 8;
        float4 lo = *(const float4*)p;
        float2 hi = *(const float2*)(p + 4);
        hh[0] += lo.x; hh[1] += lo.y; hh[2] += lo.z;
        hh[3] += lo.w; hh[4] += hi.x; hh[5] += hi.y;
    }
    float as0 = hh[0] * att_src[0] + hh[1] * att_src[1] + hh[2] * att_src[2];
    float as1 = hh[3] * att_src[3] + hh[4] * att_src[4] + hh[5] * att_src[5];
    float ad0 = hh[0] * att_dst[0] + hh[1] * att_dst[1] + hh[2] * att_dst[2];
    float ad1 = hh[3] * att_dst[3] + hh[4] * att_dst[4] + hh[5] * att_dst[5];
    g_asrc[n] = make_float2(as0, as1);
    g_adst[n] = make_float2(ad0, ad1);
    g_hh[(size_t)n * 2]     = make_float4(hh[0], hh[1], hh[2], 0.f);
    g_hh[(size_t)n * 2 + 1] = make_float4(hh[3], hh[4], hh[5], 0.f);
    float p0 = expf(lrelu(as0 + ad0));
    float p1 = expf(lrelu(as1 + ad1));
    g_acc[(size_t)n * 2]     = make_float4(p0 * hh[0], p0 * hh[1], p0 * hh[2], p0);
    g_acc[(size_t)n * 2 + 1] = make_float4(p1 * hh[3], p1 * hh[4], p1 * hh[5], p1);
}

// ---------------- K3: edge pass, 2 edges/thread, vector index loads ----------------
__global__ __launch_bounds__(256)
void k3_edge(const void* __restrict__ ei_raw) {
    int t = blockIdx.x * blockDim.x + threadIdx.x;
    int e0 = t * 2;
    if (e0 >= NE) return;
    int s[2], d[2];
    if (g_is64) {
        const longlong2* ps = (const longlong2*)((const long long*)ei_raw + e0);
        const longlong2* pdd = (const longlong2*)((const long long*)ei_raw + NE + e0);
        longlong2 sv = *ps, dv = *pdd;
        s[0] = (int)sv.x; s[1] = (int)sv.y;
        d[0] = (int)dv.x; d[1] = (int)dv.y;
    } else {
        const int2* ps = (const int2*)((const int*)ei_raw + e0);
        const int2* pdd = (const int2*)((const int*)ei_raw + NE + e0);
        int2 sv = *ps, dv = *pdd;
        s[0] = sv.x; s[1] = sv.y;
        d[0] = dv.x; d[1] = dv.y;
    }
    #pragma unroll
    for (int j = 0; j < 2; ++j) {
        float2 as = g_asrc[s[j]];
        float2 ad = g_adst[d[j]];
        float p0 = expf(lrelu(as.x + ad.x));
        float p1 = expf(lrelu(as.y + ad.y));
        float4 h0 = g_hh[(size_t)s[j] * 2];
        float4 h1 = g_hh[(size_t)s[j] * 2 + 1];
        float* base = (float*)&g_acc[(size_t)d[j] * 2];
        asm volatile("red.global.add.v4.f32 [%0], {%1,%2,%3,%4};"
                     :: "l"(base), "f"(p0 * h0.x), "f"(p0 * h0.y), "f"(p0 * h0.z), "f"(p0)
                     : "memory");
        asm volatile("red.global.add.v4.f32 [%0], {%1,%2,%3,%4};"
                     :: "l"(base + 4), "f"(p1 * h1.x), "f"(p1 * h1.y), "f"(p1 * h1.z), "f"(p1)
                     : "memory");
    }
}

// ---------------- K4: finalize ----------------
__global__ __launch_bounds__(256)
void k4_final(const float* __restrict__ bias, float* __restrict__ out) {
    int n = blockIdx.x * blockDim.x + threadIdx.x;
    if (n >= NN) return;
    float4 A = g_acc[(size_t)n * 2];
    float4 Bv = g_acc[(size_t)n * 2 + 1];
    float r0 = 1.f / A.w, r1 = 1.f / Bv.w;
    out[n * 3 + 0] = 0.5f * (A.x * r0 + Bv.x * r1) + bias[0];
    out[n * 3 + 1] = 0.5f * (A.y * r0 + Bv.y * r1) + bias[1];
    out[n * 3 + 2] = 0.5f * (A.z * r0 + Bv.z * r1) + bias[2];
}

// ---------------- launch ----------------
extern "C" void kernel_launch(void* const* d_in, const int* in_sizes, int n_in,
                              void* d_out, int out_size) {
    const float* x       = (const float*)d_in[0];
    const void*  ei      = d_in[1];
    const float* W_e1    = (const float*)d_in[2];
    const float* b_e1    = (const float*)d_in[3];
    const float* W_e2    = (const float*)d_in[4];
    const float* b_e2    = (const float*)d_in[5];
    const float* W_lin   = (const float*)d_in[6];
    const float* b_lin   = (const float*)d_in[7];
    const float* W_att   = (const float*)d_in[8];
    const float* att_src = (const float*)d_in[9];
    const float* att_dst = (const float*)d_in[10];
    const float* bias    = (const float*)d_in[11];
    float* out = (float*)d_out;

    cudaFuncSetAttribute(k1_mma, cudaFuncAttributeMaxDynamicSharedMemorySize, 2 * STAGEB);

    k_detect<<<1, 256>>>(ei);
    k_wt<<<(KIN * EH) / 256, 256>>>(W_e1);
    k0a<<<1, 256>>>(W_lin, b_lin, W_att);
    k0b<<<16, 256>>>(W_e2, b_e2);
    dim3 g1(EH / 128, (NN + 127) / 128);
    k1_mma<<<g1, 256, 2 * STAGEB>>>(x, b_e1);
    k2b<<<(NN + 255) / 256, 256>>>(att_src, att_dst);
    k3_edge<<<(NE / 2 + 255) / 256, 256>>>(ei);
    k4_final<<<(NN + 255) / 256, 256>>>(bias, out);
}

// round 15
// speedup vs baseline: 1.1411x; 1.1411x over previous
#include <cuda_runtime.h>
#include <cuda_fp16.h>
#include <cstdint>

#define NN 100000
#define NE 6400000
#define KIN 768
#define EH  512

// ---------------- scratch (static __device__, no allocations) ----------------
__device__ float4 g_hh[(size_t)NN * 2];        // hh per node (2 heads x 3 classes)
__device__ float2 g_asrc[NN];
__device__ float2 g_adst[NN];
__device__ float4 g_acc[(size_t)NN * 2];       // (num_c0,num_c1,num_c2,denom) per head
__device__ float  g_hh6b[8][(size_t)NN * 8];   // per-(bx,wn) partial h1@Wc slices (6 used, stride 8)
__device__ float  g_Wc[EH * 6 + 8];            // fused W_e2@W_lin@W_att [512,6] + bc[6]
__device__ float  g_W2[256 * 6 + 8];           // W_lin@W_att [256,6] + bl[6]
__device__ int    g_is64;
__device__ __half g_Xh[(size_t)NN * KIN];      // X as fp16
__device__ __half g_Wh[(size_t)EH * KIN];      // W_e1^T fp16 [512][768]

__device__ __forceinline__ float lrelu(float x) { return x >= 0.f ? x : 0.2f * x; }

__device__ __forceinline__ uint32_t smem_u32(const void* p) {
    uint32_t a;
    asm("{ .reg .u64 t; cvta.to.shared.u64 t, %1; cvt.u32.u64 %0, t; }" : "=r"(a) : "l"(p));
    return a;
}

#define LDSM4(r0, r1, r2, r3, addr) \
    asm volatile("ldmatrix.sync.aligned.m8n8.x4.shared.b16 {%0,%1,%2,%3}, [%4];" \
                 : "=r"(r0), "=r"(r1), "=r"(r2), "=r"(r3) : "r"(addr))

#define MMA16816(c, a0, a1, a2, a3, b0, b1) \
    asm volatile("mma.sync.aligned.m16n8k16.row.col.f32.f16.f16.f32 " \
                 "{%0,%1,%2,%3},{%4,%5,%6,%7},{%8,%9},{%0,%1,%2,%3};" \
                 : "+f"((c)[0]), "+f"((c)[1]), "+f"((c)[2]), "+f"((c)[3]) \
                 : "r"(a0), "r"(a1), "r"(a2), "r"(a3), "r"(b0), "r"(b1))

#define CP_ASYNC16(dst, src) \
    asm volatile("cp.async.cg.shared.global [%0], [%1], 16;" :: "r"(dst), "l"(src))
#define CP_COMMIT() asm volatile("cp.async.commit_group;")
#define CP_WAIT1()  asm volatile("cp.async.wait_group 1;")
#define CP_WAIT0()  asm volatile("cp.async.wait_group 0;")

// ---------------- K_detect: edge_index dtype ----------------
__global__ void k_detect(const void* __restrict__ ei) {
    const long long* p = (const long long*)ei;
    int bad = 0;
    for (int i = threadIdx.x; i < 2048; i += 256) {
        long long v = p[i];
        if (v < 0 || v >= NN) bad = 1;
    }
    bad = __syncthreads_or(bad);
    if (threadIdx.x == 0) g_is64 = !bad;
}

// ---------------- K_xcvt: X -> fp16 ----------------
__global__ void k_xcvt(const float* __restrict__ X) {
    size_t i = (size_t)blockIdx.x * 256 + threadIdx.x;   // over NN*KIN/4 float4s
    float4 v = ((const float4*)X)[i];
    __half2 a = __floats2half2_rn(v.x, v.y);
    __half2 b = __floats2half2_rn(v.z, v.w);
    ((uint2*)g_Xh)[i] = make_uint2(*(uint32_t*)&a, *(uint32_t*)&b);
}

// ---------------- K_wt: W_e1 [768][512] -> W^T fp16 [512][768] ----------------
__global__ void k_wt(const float* __restrict__ W) {
    int i = blockIdx.x * 256 + threadIdx.x;  // 0..393215
    int k = i >> 9, n = i & 511;
    g_Wh[(size_t)n * KIN + k] = __float2half_rn(W[i]);
}

// ---------------- K0a: W2 = W_lin@W_att [256,6], bl [6] ----------------
__global__ void k0a(const float* __restrict__ W_lin, const float* __restrict__ b_lin,
                    const float* __restrict__ W_att) {
    int t = threadIdx.x;  // 256
    float a[6] = {0, 0, 0, 0, 0, 0};
    for (int j = 0; j < 32; ++j) {
        float w = W_lin[t * 32 + j];
        #pragma unroll
        for (int c = 0; c < 6; ++c) a[c] += w * W_att[j * 6 + c];
    }
    #pragma unroll
    for (int c = 0; c < 6; ++c) g_W2[t * 6 + c] = a[c];
    if (t < 6) {
        float s = 0.f;
        for (int j = 0; j < 32; ++j) s += b_lin[j] * W_att[j * 6 + t];
        g_W2[256 * 6 + t] = s;
    }
}

// ---------------- K0b: Wc = W_e2@W2 [512,6], bc [6]  (grid 64 x 8 rows) ----------------
__global__ void k0b(const float* __restrict__ W_e2, const float* __restrict__ b_e2) {
    __shared__ float W2s[256 * 6];
    int t = threadIdx.x;  // 256
    #pragma unroll
    for (int j = 0; j < 6; ++j) W2s[t * 6 + j] = g_W2[t * 6 + j];
    __syncthreads();
    int row = blockIdx.x * 8 + (t >> 5);     // 8 rows per block
    int lane = t & 31;                       // 8 k-values each
    float a[6] = {0, 0, 0, 0, 0, 0};
    const float4* wr = (const float4*)(W_e2 + (size_t)row * 256 + lane * 8);
    #pragma unroll
    for (int q = 0; q < 2; ++q) {
        float4 w = wr[q];
        int k = lane * 8 + q * 4;
        #pragma unroll
        for (int c = 0; c < 6; ++c)
            a[c] += w.x * W2s[k * 6 + c] + w.y * W2s[(k + 1) * 6 + c]
                  + w.z * W2s[(k + 2) * 6 + c] + w.w * W2s[(k + 3) * 6 + c];
    }
    #pragma unroll
    for (int o = 16; o > 0; o >>= 1)
        #pragma unroll
        for (int c = 0; c < 6; ++c) a[c] += __shfl_xor_sync(0xffffffffu, a[c], o);
    if (lane == 0)
        #pragma unroll
        for (int c = 0; c < 6; ++c) g_Wc[row * 6 + c] = a[c];
    if (blockIdx.x == 0 && t < 6) {
        float s = 0.f;
        for (int k = 0; k < 256; ++k) s += b_e2[k] * g_W2[k * 6 + t];
        g_Wc[EH * 6 + t] = s + g_W2[256 * 6 + t];
    }
}

// ---------------- K1: fp16 1-term GEMM + fused relu + Wc contraction ----------------
// 128x128 tile, BK=32, double-buffered cp.async. 8 warps: wm=wid&3 (m 32), wn=wid>>2 (n 64).
#define RS 40                       // smem row stride in halves (32 + 8 pad)
#define TILEB (128 * RS * 2)        // 10240 bytes per tile
#define STAGEB (2 * TILEB)          // Xh, Wh

__global__ __launch_bounds__(256, 1)
void k1_mma(const float* __restrict__ Bb) {
    extern __shared__ __align__(16) uint8_t sm[];
    __shared__ float s_bias[128];
    __shared__ float s_wc[128 * 6];

    const int tid = threadIdx.x;
    const int wid = tid >> 5, lane = tid & 31;
    const int wm = wid & 3, wn = wid >> 2;
    const int m0 = blockIdx.y * 128;
    const int n0 = blockIdx.x * 128;
    const uint32_t smb = smem_u32(sm);

    if (tid < 128) s_bias[tid] = Bb[n0 + tid];
    for (int i = tid; i < 128 * 6; i += 256) s_wc[i] = g_Wc[n0 * 6 + i];

    const int cc = tid & 3;                 // 16B chunk within 64B row
    auto load_stage = [&](int st, int s) {
        uint32_t base = smb + st * STAGEB;
        int k0 = s * 32;
        #pragma unroll
        for (int j = 0; j < 4; ++j) {
            int buf = j >> 1;                       // 0=Xh, 1=Wh
            int r = (j & 1) * 64 + (tid >> 2);
            const __half* src;
            if (buf == 0) {
                int row = m0 + r; if (row >= NN) row = NN - 1;
                src = g_Xh + (size_t)row * KIN + k0 + cc * 8;
            } else {
                src = g_Wh + (size_t)(n0 + r) * KIN + k0 + cc * 8;
            }
            uint32_t dst = base + buf * TILEB + (r * RS + cc * 8) * 2;
            CP_ASYNC16(dst, src);
        }
        CP_COMMIT();
    };

    float c[2][8][4];
    #pragma unroll
    for (int mi = 0; mi < 2; ++mi)
        #pragma unroll
        for (int ni = 0; ni < 8; ++ni)
            #pragma unroll
            for (int q = 0; q < 4; ++q) c[mi][ni][q] = 0.f;

    load_stage(0, 0);

    int buf = 0;
    for (int s = 0; s < 24; ++s) {
        if (s + 1 < 24) { load_stage(buf ^ 1, s + 1); CP_WAIT1(); }
        else           { CP_WAIT0(); }
        __syncthreads();

        uint32_t base = smb + buf * STAGEB;
        const int arow = wm * 32 + (lane & 15);
        const int acolh = ((lane >> 4) & 1) * 8;
        const int brow = wn * 64 + ((lane >> 4) & 1) * 8 + (lane & 7);
        const int bcolh = ((lane >> 3) & 1) * 8;

        #pragma unroll
        for (int kq = 0; kq < 2; ++kq) {
            int k16 = kq * 16;
            uint32_t ah[2][4], bh[8][2];
            #pragma unroll
            for (int mi = 0; mi < 2; ++mi) {
                uint32_t aoff = ((arow + mi * 16) * RS + k16 + acolh) * 2;
                LDSM4(ah[mi][0], ah[mi][1], ah[mi][2], ah[mi][3], base + aoff);
            }
            #pragma unroll
            for (int nj = 0; nj < 4; ++nj) {
                uint32_t boff = ((brow + nj * 16) * RS + k16 + bcolh) * 2;
                LDSM4(bh[2 * nj][0], bh[2 * nj][1], bh[2 * nj + 1][0], bh[2 * nj + 1][1],
                      base + TILEB + boff);
            }
            #pragma unroll
            for (int mi = 0; mi < 2; ++mi)
                #pragma unroll
                for (int ni = 0; ni < 8; ++ni)
                    MMA16816(c[mi][ni], ah[mi][0], ah[mi][1], ah[mi][2], ah[mi][3],
                             bh[ni][0], bh[ni][1]);
        }
        __syncthreads();
        buf ^= 1;
    }

    // epilogue: bias + relu, contract against Wc[128,6], quad-reduce,
    // plain store to slice (bx*2 + wn) — each wn-half owns its own slice (no race)
    float hp[2][2][6];
    #pragma unroll
    for (int mi = 0; mi < 2; ++mi)
        #pragma unroll
        for (int r = 0; r < 2; ++r)
            #pragma unroll
            for (int k = 0; k < 6; ++k) hp[mi][r][k] = 0.f;

    const int lcolq = (lane & 3) * 2;
    #pragma unroll
    for (int mi = 0; mi < 2; ++mi)
        #pragma unroll
        for (int ni = 0; ni < 8; ++ni) {
            int colL = wn * 64 + ni * 8 + lcolq;
            float b0 = s_bias[colL], b1 = s_bias[colL + 1];
            float v00 = fmaxf(c[mi][ni][0] + b0, 0.f);
            float v01 = fmaxf(c[mi][ni][1] + b1, 0.f);
            float v10 = fmaxf(c[mi][ni][2] + b0, 0.f);
            float v11 = fmaxf(c[mi][ni][3] + b1, 0.f);
            #pragma unroll
            for (int k = 0; k < 6; ++k) {
                float w0 = s_wc[colL * 6 + k], w1 = s_wc[(colL + 1) * 6 + k];
                hp[mi][0][k] += v00 * w0 + v01 * w1;
                hp[mi][1][k] += v10 * w0 + v11 * w1;
            }
        }
    #pragma unroll
    for (int mi = 0; mi < 2; ++mi)
        #pragma unroll
        for (int r = 0; r < 2; ++r)
            #pragma unroll
            for (int k = 0; k < 6; ++k) {
                float v = hp[mi][r][k];
                v += __shfl_xor_sync(0xffffffffu, v, 1);
                v += __shfl_xor_sync(0xffffffffu, v, 2);
                hp[mi][r][k] = v;
            }
    if ((lane & 3) == 0) {
        float* slice = g_hh6b[blockIdx.x * 2 + wn];
        #pragma unroll
        for (int mi = 0; mi < 2; ++mi)
            #pragma unroll
            for (int r = 0; r < 2; ++r) {
                int row = m0 + wm * 32 + mi * 16 + r * 8 + (lane >> 2);
                if (row < NN) {
                    float* dst = slice + (size_t)row * 8;
                    *(float4*)dst = make_float4(hp[mi][r][0], hp[mi][r][1],
                                                hp[mi][r][2], hp[mi][r][3]);
                    *(float2*)(dst + 4) = make_float2(hp[mi][r][4], hp[mi][r][5]);
                }
            }
    }
}

// ---------------- K2b: sum 8 slices, node finalize (a_src/a_dst, self-loop init) ----------------
__global__ __launch_bounds__(256)
void k2b(const float* __restrict__ att_src, const float* __restrict__ att_dst) {
    int n = blockIdx.x * 256 + threadIdx.x;
    if (n >= NN) return;
    float hh[6];
    #pragma unroll
    for (int c = 0; c < 6; ++c) hh[c] = g_Wc[EH * 6 + c];
    #pragma unroll
    for (int b = 0; b < 8; ++b) {
        const float* p = g_hh6b[b] + (size_t)n * 8;
        float4 lo = *(const float4*)p;
        float2 hi = *(const float2*)(p + 4);
        hh[0] += lo.x; hh[1] += lo.y; hh[2] += lo.z;
        hh[3] += lo.w; hh[4] += hi.x; hh[5] += hi.y;
    }
    float as0 = hh[0] * att_src[0] + hh[1] * att_src[1] + hh[2] * att_src[2];
    float as1 = hh[3] * att_src[3] + hh[4] * att_src[4] + hh[5] * att_src[5];
    float ad0 = hh[0] * att_dst[0] + hh[1] * att_dst[1] + hh[2] * att_dst[2];
    float ad1 = hh[3] * att_dst[3] + hh[4] * att_dst[4] + hh[5] * att_dst[5];
    g_asrc[n] = make_float2(as0, as1);
    g_adst[n] = make_float2(ad0, ad1);
    g_hh[(size_t)n * 2]     = make_float4(hh[0], hh[1], hh[2], 0.f);
    g_hh[(size_t)n * 2 + 1] = make_float4(hh[3], hh[4], hh[5], 0.f);
    float p0 = expf(lrelu(as0 + ad0));
    float p1 = expf(lrelu(as1 + ad1));
    g_acc[(size_t)n * 2]     = make_float4(p0 * hh[0], p0 * hh[1], p0 * hh[2], p0);
    g_acc[(size_t)n * 2 + 1] = make_float4(p1 * hh[3], p1 * hh[4], p1 * hh[5], p1);
}

// ---------------- K3: edge pass, 2 edges/thread, vector index loads ----------------
__global__ __launch_bounds__(256)
void k3_edge(const void* __restrict__ ei_raw) {
    int t = blockIdx.x * blockDim.x + threadIdx.x;
    int e0 = t * 2;
    if (e0 >= NE) return;
    int s[2], d[2];
    if (g_is64) {
        const longlong2* ps = (const longlong2*)((const long long*)ei_raw + e0);
        const longlong2* pdd = (const longlong2*)((const long long*)ei_raw + NE + e0);
        longlong2 sv = *ps, dv = *pdd;
        s[0] = (int)sv.x; s[1] = (int)sv.y;
        d[0] = (int)dv.x; d[1] = (int)dv.y;
    } else {
        const int2* ps = (const int2*)((const int*)ei_raw + e0);
        const int2* pdd = (const int2*)((const int*)ei_raw + NE + e0);
        int2 sv = *ps, dv = *pdd;
        s[0] = sv.x; s[1] = sv.y;
        d[0] = dv.x; d[1] = dv.y;
    }
    #pragma unroll
    for (int j = 0; j < 2; ++j) {
        float2 as = g_asrc[s[j]];
        float2 ad = g_adst[d[j]];
        float p0 = expf(lrelu(as.x + ad.x));
        float p1 = expf(lrelu(as.y + ad.y));
        float4 h0 = g_hh[(size_t)s[j] * 2];
        float4 h1 = g_hh[(size_t)s[j] * 2 + 1];
        float* base = (float*)&g_acc[(size_t)d[j] * 2];
        asm volatile("red.global.add.v4.f32 [%0], {%1,%2,%3,%4};"
                     :: "l"(base), "f"(p0 * h0.x), "f"(p0 * h0.y), "f"(p0 * h0.z), "f"(p0)
                     : "memory");
        asm volatile("red.global.add.v4.f32 [%0], {%1,%2,%3,%4};"
                     :: "l"(base + 4), "f"(p1 * h1.x), "f"(p1 * h1.y), "f"(p1 * h1.z), "f"(p1)
                     : "memory");
    }
}

// ---------------- K4: finalize ----------------
__global__ __launch_bounds__(256)
void k4_final(const float* __restrict__ bias, float* __restrict__ out) {
    int n = blockIdx.x * blockDim.x + threadIdx.x;
    if (n >= NN) return;
    float4 A = g_acc[(size_t)n * 2];
    float4 Bv = g_acc[(size_t)n * 2 + 1];
    float r0 = 1.f / A.w, r1 = 1.f / Bv.w;
    out[n * 3 + 0] = 0.5f * (A.x * r0 + Bv.x * r1) + bias[0];
    out[n * 3 + 1] = 0.5f * (A.y * r0 + Bv.y * r1) + bias[1];
    out[n * 3 + 2] = 0.5f * (A.z * r0 + Bv.z * r1) + bias[2];
}

// ---------------- launch ----------------
extern "C" void kernel_launch(void* const* d_in, const int* in_sizes, int n_in,
                              void* d_out, int out_size) {
    const float* x       = (const float*)d_in[0];
    const void*  ei      = d_in[1];
    const float* W_e1    = (const float*)d_in[2];
    const float* b_e1    = (const float*)d_in[3];
    const float* W_e2    = (const float*)d_in[4];
    const float* b_e2    = (const float*)d_in[5];
    const float* W_lin   = (const float*)d_in[6];
    const float* b_lin   = (const float*)d_in[7];
    const float* W_att   = (const float*)d_in[8];
    const float* att_src = (const float*)d_in[9];
    const float* att_dst = (const float*)d_in[10];
    const float* bias    = (const float*)d_in[11];
    float* out = (float*)d_out;

    cudaFuncSetAttribute(k1_mma, cudaFuncAttributeMaxDynamicSharedMemorySize, 2 * STAGEB);

    k_detect<<<1, 256>>>(ei);
    k_xcvt<<<(int)((size_t)NN * KIN / 4 / 256), 256>>>(x);
    k_wt<<<(KIN * EH) / 256, 256>>>(W_e1);
    k0a<<<1, 256>>>(W_lin, b_lin, W_att);
    k0b<<<64, 256>>>(W_e2, b_e2);
    dim3 g1(EH / 128, (NN + 127) / 128);
    k1_mma<<<g1, 256, 2 * STAGEB>>>(b_e1);
    k2b<<<(NN + 255) / 256, 256>>>(att_src, att_dst);
    k3_edge<<<(NE / 2 + 255) / 256, 256>>>(ei);
    k4_final<<<(NN + 255) / 256, 256>>>(bias, out);
}

// round 17
// speedup vs baseline: 1.1493x; 1.0072x over previous
#include <cuda_runtime.h>
#include <cuda_fp16.h>
#include <cstdint>

#define NN 100000
#define NE 6400000
#define KIN 768
#define EH  512

// ---------------- scratch (static __device__, no allocations) ----------------
__device__ float4 g_hh[(size_t)NN * 2];        // hh per node (2 heads x 3 classes)
__device__ float2 g_asrc[NN];
__device__ float2 g_adst[NN];
__device__ float4 g_acc[(size_t)NN * 2];       // (num_c0,num_c1,num_c2,denom) per head
__device__ float  g_hh6b[8][(size_t)NN * 8];   // per-(bx,wn) partial h1@Wc slices (6 used, stride 8)
__device__ float  g_Wc[EH * 6 + 8];            // fused W_e2@W_lin@W_att [512,6] + bc[6]
__device__ int    g_is64;
__device__ __half g_Xh[(size_t)NN * KIN];      // X as fp16
__device__ __half g_Wh[(size_t)EH * KIN];      // W_e1^T fp16 [512][768]

__device__ __forceinline__ float lrelu(float x) { return x >= 0.f ? x : 0.2f * x; }

__device__ __forceinline__ uint32_t smem_u32(const void* p) {
    uint32_t a;
    asm("{ .reg .u64 t; cvta.to.shared.u64 t, %1; cvt.u32.u64 %0, t; }" : "=r"(a) : "l"(p));
    return a;
}

#define LDSM4(r0, r1, r2, r3, addr) \
    asm volatile("ldmatrix.sync.aligned.m8n8.x4.shared.b16 {%0,%1,%2,%3}, [%4];" \
                 : "=r"(r0), "=r"(r1), "=r"(r2), "=r"(r3) : "r"(addr))

#define MMA16816(c, a0, a1, a2, a3, b0, b1) \
    asm volatile("mma.sync.aligned.m16n8k16.row.col.f32.f16.f16.f32 " \
                 "{%0,%1,%2,%3},{%4,%5,%6,%7},{%8,%9},{%0,%1,%2,%3};" \
                 : "+f"((c)[0]), "+f"((c)[1]), "+f"((c)[2]), "+f"((c)[3]) \
                 : "r"(a0), "r"(a1), "r"(a2), "r"(a3), "r"(b0), "r"(b1))

#define CP_ASYNC16(dst, src) \
    asm volatile("cp.async.cg.shared.global [%0], [%1], 16;" :: "r"(dst), "l"(src))
#define CP_COMMIT() asm volatile("cp.async.commit_group;")
#define CP_WAIT1()  asm volatile("cp.async.wait_group 1;")
#define CP_WAIT0()  asm volatile("cp.async.wait_group 0;")

// ---------------- K_detect: edge_index dtype ----------------
__global__ void k_detect(const void* __restrict__ ei) {
    const long long* p = (const long long*)ei;
    int bad = 0;
    for (int i = threadIdx.x; i < 2048; i += 256) {
        long long v = p[i];
        if (v < 0 || v >= NN) bad = 1;
    }
    bad = __syncthreads_or(bad);
    if (threadIdx.x == 0) g_is64 = !bad;
}

// ---------------- K_xcvt: X -> fp16, 4 float4/thread for MLP ----------------
__global__ void k_xcvt(const float* __restrict__ X) {
    size_t base = (size_t)blockIdx.x * 1024 + threadIdx.x;   // over NN*KIN/4 float4s
    #pragma unroll
    for (int j = 0; j < 4; ++j) {
        size_t i = base + j * 256;
        float4 v = ((const float4*)X)[i];
        __half2 a = __floats2half2_rn(v.x, v.y);
        __half2 b = __floats2half2_rn(v.z, v.w);
        ((uint2*)g_Xh)[i] = make_uint2(*(uint32_t*)&a, *(uint32_t*)&b);
    }
}

// ---------------- K_wt: W_e1 [768][512] -> W^T fp16 [512][768] ----------------
__global__ void k_wt(const float* __restrict__ W) {
    int i = blockIdx.x * 256 + threadIdx.x;  // 0..393215
    int k = i >> 9, n = i & 511;
    g_Wh[(size_t)n * KIN + k] = __float2half_rn(W[i]);
}

// ---------------- K0: Wc = W_e2@(W_lin@W_att) [512,6] + bc  (grid 64 x 8 rows) ----------------
// each block redundantly computes W2 = W_lin@W_att [256,6] in smem (192 FMA/thread)
__global__ void k0(const float* __restrict__ W_e2, const float* __restrict__ b_e2,
                   const float* __restrict__ W_lin, const float* __restrict__ b_lin,
                   const float* __restrict__ W_att) {
    __shared__ float W2s[256 * 6];
    int t = threadIdx.x;  // 256
    {
        float a[6] = {0, 0, 0, 0, 0, 0};
        #pragma unroll 4
        for (int j = 0; j < 32; ++j) {
            float w = W_lin[t * 32 + j];
            #pragma unroll
            for (int c = 0; c < 6; ++c) a[c] += w * W_att[j * 6 + c];
        }
        #pragma unroll
        for (int c = 0; c < 6; ++c) W2s[t * 6 + c] = a[c];
    }
    __syncthreads();
    int row = blockIdx.x * 8 + (t >> 5);     // 8 rows per block
    int lane = t & 31;                       // 8 k-values each
    float a[6] = {0, 0, 0, 0, 0, 0};
    const float4* wr = (const float4*)(W_e2 + (size_t)row * 256 + lane * 8);
    #pragma unroll
    for (int q = 0; q < 2; ++q) {
        float4 w = wr[q];
        int k = lane * 8 + q * 4;
        #pragma unroll
        for (int c = 0; c < 6; ++c)
            a[c] += w.x * W2s[k * 6 + c] + w.y * W2s[(k + 1) * 6 + c]
                  + w.z * W2s[(k + 2) * 6 + c] + w.w * W2s[(k + 3) * 6 + c];
    }
    #pragma unroll
    for (int o = 16; o > 0; o >>= 1)
        #pragma unroll
        for (int c = 0; c < 6; ++c) a[c] += __shfl_xor_sync(0xffffffffu, a[c], o);
    if (lane == 0)
        #pragma unroll
        for (int c = 0; c < 6; ++c) g_Wc[row * 6 + c] = a[c];
    if (blockIdx.x == 0 && t < 6) {
        float bl = 0.f;
        for (int j = 0; j < 32; ++j) bl += b_lin[j] * W_att[j * 6 + t];
        float s = 0.f;
        for (int k = 0; k < 256; ++k) s += b_e2[k] * W2s[k * 6 + t];
        g_Wc[EH * 6 + t] = s + bl;
    }
}

// ---------------- K1: fp16 1-term GEMM + fused relu + Wc contraction ----------------
// 128x128 tile, BK=32, TRIPLE-buffered cp.async (1 barrier/stage).
// 8 warps: wm=wid&3 (m 32), wn=wid>>2 (n 64).
#define RS 40                       // smem row stride in halves (32 + 8 pad)
#define TILEB (128 * RS * 2)        // 10240 bytes per tile
#define STAGEB (2 * TILEB)          // Xh, Wh
#define NSTG 3

__global__ __launch_bounds__(256, 1)
void k1_mma(const float* __restrict__ Bb) {
    extern __shared__ __align__(16) uint8_t sm[];
    __shared__ float s_bias[128];
    __shared__ float s_wc[128 * 6];

    const int tid = threadIdx.x;
    const int wid = tid >> 5, lane = tid & 31;
    const int wm = wid & 3, wn = wid >> 2;
    const int m0 = blockIdx.y * 128;
    const int n0 = blockIdx.x * 128;
    const uint32_t smb = smem_u32(sm);

    if (tid < 128) s_bias[tid] = Bb[n0 + tid];
    for (int i = tid; i < 128 * 6; i += 256) s_wc[i] = g_Wc[n0 * 6 + i];

    const int cc = tid & 3;                 // 16B chunk within 64B row
    auto load_stage = [&](int st, int s) {
        uint32_t base = smb + st * STAGEB;
        int k0 = s * 32;
        #pragma unroll
        for (int j = 0; j < 4; ++j) {
            int buf = j >> 1;                       // 0=Xh, 1=Wh
            int r = (j & 1) * 64 + (tid >> 2);
            const __half* src;
            if (buf == 0) {
                int row = m0 + r; if (row >= NN) row = NN - 1;
                src = g_Xh + (size_t)row * KIN + k0 + cc * 8;
            } else {
                src = g_Wh + (size_t)(n0 + r) * KIN + k0 + cc * 8;
            }
            uint32_t dst = base + buf * TILEB + (r * RS + cc * 8) * 2;
            CP_ASYNC16(dst, src);
        }
        CP_COMMIT();
    };

    float c[2][8][4];
    #pragma unroll
    for (int mi = 0; mi < 2; ++mi)
        #pragma unroll
        for (int ni = 0; ni < 8; ++ni)
            #pragma unroll
            for (int q = 0; q < 4; ++q) c[mi][ni][q] = 0.f;

    load_stage(0, 0);
    load_stage(1, 1);

    int cur = 0;                             // stage s lives in buffer s%3
    for (int s = 0; s < 24; ++s) {
        if (s + 1 < 24) CP_WAIT1(); else CP_WAIT0();
        __syncthreads();                     // all warps done reading buffer (s+2)%3 (read at s-1)
        if (s + 2 < 24) {
            int nb = cur + 2; if (nb >= NSTG) nb -= NSTG;
            load_stage(nb, s + 2);
        }

        uint32_t base = smb + cur * STAGEB;
        const int arow = wm * 32 + (lane & 15);
        const int acolh = ((lane >> 4) & 1) * 8;
        const int brow = wn * 64 + ((lane >> 4) & 1) * 8 + (lane & 7);
        const int bcolh = ((lane >> 3) & 1) * 8;

        #pragma unroll
        for (int kq = 0; kq < 2; ++kq) {
            int k16 = kq * 16;
            uint32_t ah[2][4], bh[8][2];
            #pragma unroll
            for (int mi = 0; mi < 2; ++mi) {
                uint32_t aoff = ((arow + mi * 16) * RS + k16 + acolh) * 2;
                LDSM4(ah[mi][0], ah[mi][1], ah[mi][2], ah[mi][3], base + aoff);
            }
            #pragma unroll
            for (int nj = 0; nj < 4; ++nj) {
                uint32_t boff = ((brow + nj * 16) * RS + k16 + bcolh) * 2;
                LDSM4(bh[2 * nj][0], bh[2 * nj][1], bh[2 * nj + 1][0], bh[2 * nj + 1][1],
                      base + TILEB + boff);
            }
            #pragma unroll
            for (int mi = 0; mi < 2; ++mi)
                #pragma unroll
                for (int ni = 0; ni < 8; ++ni)
                    MMA16816(c[mi][ni], ah[mi][0], ah[mi][1], ah[mi][2], ah[mi][3],
                             bh[ni][0], bh[ni][1]);
        }
        if (++cur >= NSTG) cur = 0;
    }

    // epilogue: bias + relu, contract against Wc[128,6], quad-reduce,
    // plain store to slice (bx*2 + wn) — each wn-half owns its own slice (no race)
    float hp[2][2][6];
    #pragma unroll
    for (int mi = 0; mi < 2; ++mi)
        #pragma unroll
        for (int r = 0; r < 2; ++r)
            #pragma unroll
            for (int k = 0; k < 6; ++k) hp[mi][r][k] = 0.f;

    const int lcolq = (lane & 3) * 2;
    #pragma unroll
    for (int mi = 0; mi < 2; ++mi)
        #pragma unroll
        for (int ni = 0; ni < 8; ++ni) {
            int colL = wn * 64 + ni * 8 + lcolq;
            float b0 = s_bias[colL], b1 = s_bias[colL + 1];
            float v00 = fmaxf(c[mi][ni][0] + b0, 0.f);
            float v01 = fmaxf(c[mi][ni][1] + b1, 0.f);
            float v10 = fmaxf(c[mi][ni][2] + b0, 0.f);
            float v11 = fmaxf(c[mi][ni][3] + b1, 0.f);
            #pragma unroll
            for (int k = 0; k < 6; ++k) {
                float w0 = s_wc[colL * 6 + k], w1 = s_wc[(colL + 1) * 6 + k];
                hp[mi][0][k] += v00 * w0 + v01 * w1;
                hp[mi][1][k] += v10 * w0 + v11 * w1;
            }
        }
    #pragma unroll
    for (int mi = 0; mi < 2; ++mi)
        #pragma unroll
        for (int r = 0; r < 2; ++r)
            #pragma unroll
            for (int k = 0; k < 6; ++k) {
                float v = hp[mi][r][k];
                v += __shfl_xor_sync(0xffffffffu, v, 1);
                v += __shfl_xor_sync(0xffffffffu, v, 2);
                hp[mi][r][k] = v;
            }
    if ((lane & 3) == 0) {
        float* slice = g_hh6b[blockIdx.x * 2 + wn];
        #pragma unroll
        for (int mi = 0; mi < 2; ++mi)
            #pragma unroll
            for (int r = 0; r < 2; ++r) {
                int row = m0 + wm * 32 + mi * 16 + r * 8 + (lane >> 2);
                if (row < NN) {
                    float* dst = slice + (size_t)row * 8;
                    *(float4*)dst = make_float4(hp[mi][r][0], hp[mi][r][1],
                                                hp[mi][r][2], hp[mi][r][3]);
                    *(float2*)(dst + 4) = make_float2(hp[mi][r][4], hp[mi][r][5]);
                }
            }
    }
}

// ---------------- K2b: sum 8 slices, node finalize (a_src/a_dst, self-loop init) ----------------
__global__ __launch_bounds__(256)
void k2b(const float* __restrict__ att_src, const float* __restrict__ att_dst) {
    int n = blockIdx.x * 256 + threadIdx.x;
    if (n >= NN) return;
    float hh[6];
    #pragma unroll
    for (int c = 0; c < 6; ++c) hh[c] = g_Wc[EH * 6 + c];
    #pragma unroll
    for (int b = 0; b < 8; ++b) {
        const float* p = g_hh6b[b] + (size_t)n * 8;
        float4 lo = *(const float4*)p;
        float2 hi = *(const float2*)(p + 4);
        hh[0] += lo.x; hh[1] += lo.y; hh[2] += lo.z;
        hh[3] += lo.w; hh[4] += hi.x; hh[5] += hi.y;
    }
    float as0 = hh[0] * att_src[0] + hh[1] * att_src[1] + hh[2] * att_src[2];
    float as1 = hh[3] * att_src[3] + hh[4] * att_src[4] + hh[5] * att_src[5];
    float ad0 = hh[0] * att_dst[0] + hh[1] * att_dst[1] + hh[2] * att_dst[2];
    float ad1 = hh[3] * att_dst[3] + hh[4] * att_dst[4] + hh[5] * att_dst[5];
    g_asrc[n] = make_float2(as0, as1);
    g_adst[n] = make_float2(ad0, ad1);
    g_hh[(size_t)n * 2]     = make_float4(hh[0], hh[1], hh[2], 0.f);
    g_hh[(size_t)n * 2 + 1] = make_float4(hh[3], hh[4], hh[5], 0.f);
    float p0 = expf(lrelu(as0 + ad0));
    float p1 = expf(lrelu(as1 + ad1));
    g_acc[(size_t)n * 2]     = make_float4(p0 * hh[0], p0 * hh[1], p0 * hh[2], p0);
    g_acc[(size_t)n * 2 + 1] = make_float4(p1 * hh[3], p1 * hh[4], p1 * hh[5], p1);
}

// ---------------- K3: edge pass, 2 edges/thread, vector index loads ----------------
__global__ __launch_bounds__(256)
void k3_edge(const void* __restrict__ ei_raw) {
    int t = blockIdx.x * blockDim.x + threadIdx.x;
    int e0 = t * 2;
    if (e0 >= NE) return;
    int s[2], d[2];
    if (g_is64) {
        const longlong2* ps = (const longlong2*)((const long long*)ei_raw + e0);
        const longlong2* pdd = (const longlong2*)((const long long*)ei_raw + NE + e0);
        longlong2 sv = *ps, dv = *pdd;
        s[0] = (int)sv.x; s[1] = (int)sv.y;
        d[0] = (int)dv.x; d[1] = (int)dv.y;
    } else {
        const int2* ps = (const int2*)((const int*)ei_raw + e0);
        const int2* pdd = (const int2*)((const int*)ei_raw + NE + e0);
        int2 sv = *ps, dv = *pdd;
        s[0] = sv.x; s[1] = sv.y;
        d[0] = dv.x; d[1] = dv.y;
    }
    #pragma unroll
    for (int j = 0; j < 2; ++j) {
        float2 as = g_asrc[s[j]];
        float2 ad = g_adst[d[j]];
        float p0 = expf(lrelu(as.x + ad.x));
        float p1 = expf(lrelu(as.y + ad.y));
        float4 h0 = g_hh[(size_t)s[j] * 2];
        float4 h1 = g_hh[(size_t)s[j] * 2 + 1];
        float* base = (float*)&g_acc[(size_t)d[j] * 2];
        asm volatile("red.global.add.v4.f32 [%0], {%1,%2,%3,%4};"
                     :: "l"(base), "f"(p0 * h0.x), "f"(p0 * h0.y), "f"(p0 * h0.z), "f"(p0)
                     : "memory");
        asm volatile("red.global.add.v4.f32 [%0], {%1,%2,%3,%4};"
                     :: "l"(base + 4), "f"(p1 * h1.x), "f"(p1 * h1.y), "f"(p1 * h1.z), "f"(p1)
                     : "memory");
    }
}

// ---------------- K4: finalize ----------------
__global__ __launch_bounds__(256)
void k4_final(const float* __restrict__ bias, float* __restrict__ out) {
    int n = blockIdx.x * blockDim.x + threadIdx.x;
    if (n >= NN) return;
    float4 A = g_acc[(size_t)n * 2];
    float4 Bv = g_acc[(size_t)n * 2 + 1];
    float r0 = 1.f / A.w, r1 = 1.f / Bv.w;
    out[n * 3 + 0] = 0.5f * (A.x * r0 + Bv.x * r1) + bias[0];
    out[n * 3 + 1] = 0.5f * (A.y * r0 + Bv.y * r1) + bias[1];
    out[n * 3 + 2] = 0.5f * (A.z * r0 + Bv.z * r1) + bias[2];
}

// ---------------- launch ----------------
extern "C" void kernel_launch(void* const* d_in, const int* in_sizes, int n_in,
                              void* d_out, int out_size) {
    const float* x       = (const float*)d_in[0];
    const void*  ei      = d_in[1];
    const float* W_e1    = (const float*)d_in[2];
    const float* b_e1    = (const float*)d_in[3];
    const float* W_e2    = (const float*)d_in[4];
    const float* b_e2    = (const float*)d_in[5];
    const float* W_lin   = (const float*)d_in[6];
    const float* b_lin   = (const float*)d_in[7];
    const float* W_att   = (const float*)d_in[8];
    const float* att_src = (const float*)d_in[9];
    const float* att_dst = (const float*)d_in[10];
    const float* bias    = (const float*)d_in[11];
    float* out = (float*)d_out;

    cudaFuncSetAttribute(k1_mma, cudaFuncAttributeMaxDynamicSharedMemorySize, NSTG * STAGEB);

    k_detect<<<1, 256>>>(ei);
    k_xcvt<<<(int)((size_t)NN * KIN / 4 / 1024), 256>>>(x);
    k_wt<<<(KIN * EH) / 256, 256>>>(W_e1);
    k0<<<64, 256>>>(W_e2, b_e2, W_lin, b_lin, W_att);
    dim3 g1(EH / 128, (NN + 127) / 128);
    k1_mma<<<g1, 256, NSTG * STAGEB>>>(b_e1);
    k2b<<<(NN + 255) / 256, 256>>>(att_src, att_dst);
    k3_edge<<<(NE / 2 + 255) / 256, 256>>>(ei);
    k4_final<<<(NN + 255) / 256, 256>>>(bias, out);
}